// round 1
// baseline (speedup 1.0000x reference)
#include <cuda_runtime.h>
#include <cuda_bf16.h>
#include <cstdint>

#define D_IN 1024
#define H    4096   // H1 == H2 == 4096

// ---------------- device scratch (no allocation allowed) ----------------
__device__ __align__(16) float g_W1s[H * D_IN];   // s[h] * W1[h,i]  (16 MB)
__device__ __align__(16) float g_u0[H];
__device__ __align__(16) float g_w[H];            // c[h]*r[h] = -2 u0 s * ||W1 row||^2
__device__ __align__(16) float g_v0[H];
__device__ __align__(16) float g_t[H];
__device__ __align__(16) float g_part1[H];
__device__ __align__(16) float g_qpart[8 * H];    // per-N-tile partial row sq-norms

// ---------------- K1: layer-1 GEMV + r + scaled W1 ----------------
__global__ __launch_bounds__(256) void k1_layer1(const float* __restrict__ x,
                                                 const float* __restrict__ W1,
                                                 const float* __restrict__ b1) {
    int warp = threadIdx.x >> 5, lane = threadIdx.x & 31;
    int h = blockIdx.x * 8 + warp;
    const float4* row = (const float4*)(W1 + (size_t)h * D_IN);
    const float4* xv  = (const float4*)x;
    float4 buf[8];
    float dot = 0.f, sq = 0.f;
#pragma unroll
    for (int it = 0; it < 8; it++) {
        float4 wv = row[it * 32 + lane];
        float4 xw = xv[it * 32 + lane];
        buf[it] = wv;
        dot += wv.x * xw.x + wv.y * xw.y + wv.z * xw.z + wv.w * xw.w;
        sq  += wv.x * wv.x + wv.y * wv.y + wv.z * wv.z + wv.w * wv.w;
    }
#pragma unroll
    for (int off = 16; off; off >>= 1) {
        dot += __shfl_down_sync(0xffffffffu, dot, off);
        sq  += __shfl_down_sync(0xffffffffu, sq,  off);
    }
    float sv = 0.f;
    if (lane == 0) {
        float a0 = dot + b1[h];
        float u0 = tanhf(a0);
        sv = 1.f - u0 * u0;
        g_u0[h] = u0;
        g_w[h]  = -2.f * u0 * sv * sq;
    }
    sv = __shfl_sync(0xffffffffu, sv, 0);
    float4* out = (float4*)(g_W1s + (size_t)h * D_IN);
#pragma unroll
    for (int it = 0; it < 8; it++) {
        float4 v = buf[it];
        v.x *= sv; v.y *= sv; v.z *= sv; v.w *= sv;
        out[it * 32 + lane] = v;
    }
}

// ---------------- K2: fused dual GEMV over W2 (z0 and part1) ----------------
__global__ __launch_bounds__(256) void k2_layer2(const float* __restrict__ W2,
                                                 const float* __restrict__ b2) {
    int warp = threadIdx.x >> 5, lane = threadIdx.x & 31;
    int j = blockIdx.x * 8 + warp;
    const float4* row = (const float4*)(W2 + (size_t)j * H);
    const float4* u0v = (const float4*)g_u0;
    const float4* wv4 = (const float4*)g_w;
    float d1 = 0.f, d2 = 0.f;
#pragma unroll 8
    for (int it = 0; it < 32; it++) {
        float4 a = row[it * 32 + lane];
        float4 u = u0v[it * 32 + lane];
        float4 w = wv4[it * 32 + lane];
        d1 += a.x * u.x + a.y * u.y + a.z * u.z + a.w * u.w;
        d2 += a.x * w.x + a.y * w.y + a.z * w.z + a.w * w.w;
    }
#pragma unroll
    for (int off = 16; off; off >>= 1) {
        d1 += __shfl_down_sync(0xffffffffu, d1, off);
        d2 += __shfl_down_sync(0xffffffffu, d2, off);
    }
    if (lane == 0) {
        float z0 = d1 + b2[j];
        float v0 = tanhf(z0);
        g_v0[j] = v0;
        g_t[j] = 1.f - v0 * v0;
        g_part1[j] = d2;
    }
}

// ---------------- K3: tf32 GEMM  M=W2 * W1s, fused row sq-norm epilogue ----------------
__device__ __forceinline__ void cp16(void* sdst, const void* gsrc) {
    uint32_t sa = (uint32_t)__cvta_generic_to_shared(sdst);
    asm volatile("cp.async.cg.shared.global [%0], [%1], 16;\n" :: "r"(sa), "l"(gsrc));
}
__device__ __forceinline__ uint32_t f2tf(float x) {
    uint32_t u; asm("cvt.rna.tf32.f32 %0, %1;" : "=r"(u) : "f"(x)); return u;
}

#define BM 128
#define BN 128
#define BK 16
#define AS_S 20    // padded A stride: (20*m + k) % 32 unique per fragment quad
#define BS_S 132   // padded B stride: (132 = 4 mod 32) -> unique banks

__global__ __launch_bounds__(256) void k3_gemm_q(const float* __restrict__ W2) {
    __shared__ float As[2][BM][AS_S];
    __shared__ float Bs[2][BK][BS_S];
    const int bn = blockIdx.x, bm = blockIdx.y;
    const int tid = threadIdx.x;
    const int lane = tid & 31, wid = tid >> 5;
    const int warpM = wid >> 1, warpN = wid & 1;   // warp tile 32 x 64
    const int gid = lane >> 2, tig = lane & 3;

    const int a_r = tid >> 2;          // 0..63
    const int a_k = (tid & 3) * 4;     // 0,4,8,12
    const int b_n = (tid & 31) * 4;    // 0..124
    const int b_k = tid >> 5;          // 0..7

    const float* Ag = W2 + (size_t)(bm * BM) * H;
    const float* Bg = g_W1s;

    float acc[2][8][4];
#pragma unroll
    for (int mi = 0; mi < 2; mi++)
#pragma unroll
        for (int ni = 0; ni < 8; ni++)
#pragma unroll
            for (int r = 0; r < 4; r++) acc[mi][ni][r] = 0.f;

    auto load_tiles = [&](int st, int kt) {
        const float* abase = Ag + kt * BK + a_k;
#pragma unroll
        for (int i = 0; i < 2; i++) {
            int r = a_r + 64 * i;
            cp16(&As[st][r][a_k], abase + (size_t)r * H);
        }
        const float* bbase = Bg + (size_t)(kt * BK) * D_IN + bn * BN + b_n;
#pragma unroll
        for (int i = 0; i < 2; i++) {
            int k = b_k + 8 * i;
            cp16(&Bs[st][k][b_n], bbase + (size_t)k * D_IN);
        }
    };

    load_tiles(0, 0);
    asm volatile("cp.async.commit_group;\n");

    const int KT = H / BK;  // 256
    for (int kt = 0; kt < KT; kt++) {
        const int cur = kt & 1;
        if (kt + 1 < KT) {
            load_tiles(cur ^ 1, kt + 1);
            asm volatile("cp.async.commit_group;\n");
            asm volatile("cp.async.wait_group 1;\n");
        } else {
            asm volatile("cp.async.wait_group 0;\n");
        }
        __syncthreads();

#pragma unroll
        for (int ks = 0; ks < 2; ks++) {
            const int kb = ks * 8;
            uint32_t af[2][4];
#pragma unroll
            for (int mi = 0; mi < 2; mi++) {
                int m = warpM * 32 + mi * 16;
                af[mi][0] = f2tf(As[cur][m + gid    ][kb + tig    ]);
                af[mi][1] = f2tf(As[cur][m + gid + 8][kb + tig    ]);
                af[mi][2] = f2tf(As[cur][m + gid    ][kb + tig + 4]);
                af[mi][3] = f2tf(As[cur][m + gid + 8][kb + tig + 4]);
            }
            uint32_t bf[8][2];
#pragma unroll
            for (int ni = 0; ni < 8; ni++) {
                int n = warpN * 64 + ni * 8 + gid;
                bf[ni][0] = f2tf(Bs[cur][kb + tig    ][n]);
                bf[ni][1] = f2tf(Bs[cur][kb + tig + 4][n]);
            }
#pragma unroll
            for (int mi = 0; mi < 2; mi++)
#pragma unroll
                for (int ni = 0; ni < 8; ni++) {
                    float* c = acc[mi][ni];
                    asm volatile(
                        "mma.sync.aligned.m16n8k8.row.col.f32.tf32.tf32.f32 "
                        "{%0,%1,%2,%3}, {%4,%5,%6,%7}, {%8,%9}, {%0,%1,%2,%3};\n"
                        : "+f"(c[0]), "+f"(c[1]), "+f"(c[2]), "+f"(c[3])
                        : "r"(af[mi][0]), "r"(af[mi][1]), "r"(af[mi][2]), "r"(af[mi][3]),
                          "r"(bf[ni][0]), "r"(bf[ni][1]));
                }
        }
        __syncthreads();
    }

    // Epilogue: per-row sum of squares over this CTA's 128 columns (deterministic).
    float* qs = &As[0][0][0];  // reuse smem: 2 slices x 128 rows
#pragma unroll
    for (int mi = 0; mi < 2; mi++) {
        float p0 = 0.f, p1 = 0.f;
#pragma unroll
        for (int ni = 0; ni < 8; ni++) {
            p0 += acc[mi][ni][0] * acc[mi][ni][0] + acc[mi][ni][1] * acc[mi][ni][1];
            p1 += acc[mi][ni][2] * acc[mi][ni][2] + acc[mi][ni][3] * acc[mi][ni][3];
        }
        p0 += __shfl_xor_sync(0xffffffffu, p0, 1);
        p0 += __shfl_xor_sync(0xffffffffu, p0, 2);
        p1 += __shfl_xor_sync(0xffffffffu, p1, 1);
        p1 += __shfl_xor_sync(0xffffffffu, p1, 2);
        if (tig == 0) {
            int r = warpM * 32 + mi * 16 + gid;
            qs[warpN * 128 + r]     = p0;
            qs[warpN * 128 + r + 8] = p1;
        }
    }
    __syncthreads();
    if (tid < 128) {
        float q = qs[tid] + qs[128 + tid];
        g_qpart[bn * H + bm * BM + tid] = q;
    }
}

// ---------------- K4: final reduction ----------------
__global__ __launch_bounds__(256) void k4_final(const float* __restrict__ W3,
                                                float* __restrict__ out) {
    int tid = threadIdx.x;
    float local = 0.f;
    for (int j = tid; j < H; j += 256) {
        float q = 0.f;
#pragma unroll
        for (int nt = 0; nt < 8; nt++) q += g_qpart[nt * H + j];
        local += W3[j] * g_t[j] * (g_part1[j] - 2.f * g_v0[j] * q);
    }
    __shared__ float red[256];
    red[tid] = local;
    __syncthreads();
    for (int s = 128; s; s >>= 1) {
        if (tid < s) red[tid] += red[tid + s];
        __syncthreads();
    }
    if (tid == 0) out[0] = red[0];
}

// ---------------- launch ----------------
extern "C" void kernel_launch(void* const* d_in, const int* in_sizes, int n_in,
                              void* d_out, int out_size) {
    const float* x  = (const float*)d_in[0];
    const float* W1 = (const float*)d_in[1];
    const float* b1 = (const float*)d_in[2];
    const float* W2 = (const float*)d_in[3];
    const float* b2 = (const float*)d_in[4];
    const float* W3 = (const float*)d_in[5];
    // b3 (d_in[6]) does not appear in the Laplacian
    float* out = (float*)d_out;

    k1_layer1<<<H / 8, 256>>>(x, W1, b1);
    k2_layer2<<<H / 8, 256>>>(W2, b2);
    dim3 g3(D_IN / BN, H / BM);  // (8, 32)
    k3_gemm_q<<<g3, 256>>>(W2);
    k4_final<<<1, 256>>>(W3, out);
}

// round 4
// speedup vs baseline: 2.3396x; 2.3396x over previous
#include <cuda_runtime.h>
#include <cuda.h>
#include <cuda_bf16.h>
#include <cstdint>

#define D_IN 1024
#define H    4096

// ---------------- device scratch ----------------
__device__ __align__(1024) __nv_bfloat16 g_W1sT[D_IN * H];  // [i][h] = bf16(s[h]*W1[h][i])
__device__ __align__(1024) __nv_bfloat16 g_W2h[H * H];      // bf16 copy of W2
__device__ __align__(16) float g_u0[H];
__device__ __align__(16) float g_w[H];
__device__ __align__(16) float g_v0[H];
__device__ __align__(16) float g_t[H];
__device__ __align__(16) float g_part1[H];
__device__ __align__(16) float g_qpart[4 * H];
__device__ __align__(16) float g_red[32];

// ---------------- PTX helpers ----------------
__device__ __forceinline__ uint32_t smem_u32(const void* p) {
    uint32_t a;
    asm("{ .reg .u64 t; cvta.to.shared.u64 t, %1; cvt.u32.u64 %0, t; }" : "=r"(a) : "l"(p));
    return a;
}
__device__ __forceinline__ uint32_t elect_one() {
    uint32_t p;
    asm volatile("{ .reg .pred P; elect.sync _|P, 0xFFFFFFFF; selp.b32 %0, 1, 0, P; }" : "=r"(p));
    return p;
}
__device__ __forceinline__ void mbar_init(uint32_t mbar, uint32_t cnt) {
    asm volatile("mbarrier.init.shared.b64 [%0], %1;" :: "r"(mbar), "r"(cnt) : "memory");
}
__device__ __forceinline__ void mbar_expect_tx(uint32_t mbar, uint32_t bytes) {
    asm volatile("mbarrier.arrive.expect_tx.shared.b64 _, [%0], %1;" :: "r"(mbar), "r"(bytes) : "memory");
}
__device__ __forceinline__ void mbar_arrive(uint32_t mbar) {
    asm volatile("mbarrier.arrive.shared.b64 _, [%0];" :: "r"(mbar) : "memory");
}
__device__ __forceinline__ void mbar_wait(uint32_t mbar, uint32_t parity) {
    asm volatile(
        "{\n\t.reg .pred P;\n\t"
        "W%=:\n\t"
        "mbarrier.try_wait.parity.acquire.cta.shared::cta.b64 P, [%0], %1, 0x989680;\n\t"
        "@!P bra W%=;\n\t}"
        :: "r"(mbar), "r"(parity) : "memory");
}
__device__ __forceinline__ void tma2d(uint32_t sdst, const void* map, int cx, int cy, uint32_t mbar) {
    asm volatile(
        "cp.async.bulk.tensor.2d.shared::cta.global.tile.mbarrier::complete_tx::bytes "
        "[%0], [%1, {%2, %3}], [%4];"
        :: "r"(sdst), "l"(map), "r"(cx), "r"(cy), "r"(mbar) : "memory");
}
__device__ __forceinline__ void ldsm4(uint32_t* r, uint32_t addr) {
    asm volatile("ldmatrix.sync.aligned.m8n8.x4.shared.b16 {%0,%1,%2,%3}, [%4];"
                 : "=r"(r[0]), "=r"(r[1]), "=r"(r[2]), "=r"(r[3]) : "r"(addr));
}
__device__ __forceinline__ void mma_bf16(float* c, const uint32_t* a, uint32_t b0, uint32_t b1) {
    asm volatile(
        "mma.sync.aligned.m16n8k16.row.col.f32.bf16.bf16.f32 "
        "{%0,%1,%2,%3}, {%4,%5,%6,%7}, {%8,%9}, {%0,%1,%2,%3};"
        : "+f"(c[0]), "+f"(c[1]), "+f"(c[2]), "+f"(c[3])
        : "r"(a[0]), "r"(a[1]), "r"(a[2]), "r"(a[3]), "r"(b0), "r"(b1));
}
__device__ __forceinline__ uint32_t swz(uint32_t off) { return off ^ ((off >> 3) & 0x70); }

// ---------------- K1: layer-1 GEMV + r + bf16 scaled-transposed W1 ----------------
__global__ __launch_bounds__(256) void k1_layer1(const float* __restrict__ x,
                                                 const float* __restrict__ W1,
                                                 const float* __restrict__ b1) {
    __shared__ float rows[8][1024];
    int warp = threadIdx.x >> 5, lane = threadIdx.x & 31, tid = threadIdx.x;
    int h = blockIdx.x * 8 + warp;
    const float4* row = (const float4*)(W1 + (size_t)h * D_IN);
    const float4* xv  = (const float4*)x;
    float4 buf[8];
    float dot = 0.f, sq = 0.f;
#pragma unroll
    for (int it = 0; it < 8; it++) {
        float4 wv = row[it * 32 + lane];
        float4 xw = xv[it * 32 + lane];
        buf[it] = wv;
        dot += wv.x * xw.x + wv.y * xw.y + wv.z * xw.z + wv.w * xw.w;
        sq  += wv.x * wv.x + wv.y * wv.y + wv.z * wv.z + wv.w * wv.w;
    }
#pragma unroll
    for (int off = 16; off; off >>= 1) {
        dot += __shfl_down_sync(0xffffffffu, dot, off);
        sq  += __shfl_down_sync(0xffffffffu, sq,  off);
    }
    float sv = 0.f;
    if (lane == 0) {
        float a0 = dot + b1[h];
        float u0 = tanhf(a0);
        sv = 1.f - u0 * u0;
        g_u0[h] = u0;
        g_w[h]  = -2.f * u0 * sv * sq;
    }
    sv = __shfl_sync(0xffffffffu, sv, 0);
#pragma unroll
    for (int it = 0; it < 8; it++) {
        float4 v = buf[it];
        v.x *= sv; v.y *= sv; v.z *= sv; v.w *= sv;
        *(float4*)&rows[warp][it * 128 + lane * 4] = v;
    }
    __syncthreads();
    int h0 = blockIdx.x * 8;
#pragma unroll
    for (int r = 0; r < 4; r++) {
        int i = tid + r * 256;
        __nv_bfloat162 p0 = __floats2bfloat162_rn(rows[0][i], rows[1][i]);
        __nv_bfloat162 p1 = __floats2bfloat162_rn(rows[2][i], rows[3][i]);
        __nv_bfloat162 p2 = __floats2bfloat162_rn(rows[4][i], rows[5][i]);
        __nv_bfloat162 p3 = __floats2bfloat162_rn(rows[6][i], rows[7][i]);
        uint4 u;
        u.x = *(uint32_t*)&p0; u.y = *(uint32_t*)&p1;
        u.z = *(uint32_t*)&p2; u.w = *(uint32_t*)&p3;
        *(uint4*)(g_W1sT + (size_t)i * H + h0) = u;
    }
}

// ---------------- K2: dual GEMV over W2 + bf16 conversion ----------------
__global__ __launch_bounds__(256) void k2_layer2(const float* __restrict__ W2,
                                                 const float* __restrict__ b2) {
    int warp = threadIdx.x >> 5, lane = threadIdx.x & 31;
    int j = blockIdx.x * 8 + warp;
    const float4* row = (const float4*)(W2 + (size_t)j * H);
    const float4* u0v = (const float4*)g_u0;
    const float4* wv4 = (const float4*)g_w;
    __nv_bfloat16* wout = g_W2h + (size_t)j * H;
    float d1 = 0.f, d2 = 0.f;
#pragma unroll 4
    for (int it = 0; it < 32; it++) {
        float4 a = row[it * 32 + lane];
        float4 u = u0v[it * 32 + lane];
        float4 w = wv4[it * 32 + lane];
        d1 += a.x * u.x + a.y * u.y + a.z * u.z + a.w * u.w;
        d2 += a.x * w.x + a.y * w.y + a.z * w.z + a.w * w.w;
        __nv_bfloat162 q0 = __floats2bfloat162_rn(a.x, a.y);
        __nv_bfloat162 q1 = __floats2bfloat162_rn(a.z, a.w);
        uint2 uo; uo.x = *(uint32_t*)&q0; uo.y = *(uint32_t*)&q1;
        *(uint2*)(wout + it * 128 + lane * 4) = uo;
    }
#pragma unroll
    for (int off = 16; off; off >>= 1) {
        d1 += __shfl_down_sync(0xffffffffu, d1, off);
        d2 += __shfl_down_sync(0xffffffffu, d2, off);
    }
    if (lane == 0) {
        float z0 = d1 + b2[j];
        float v0 = tanhf(z0);
        g_v0[j] = v0;
        g_t[j] = 1.f - v0 * v0;
        g_part1[j] = d2;
    }
}

// ---------------- K3: TMA + mma.sync bf16 GEMM, fused square-reduce ----------------
#define BM3 128
#define BN3 256
#define KS3 64                       // bf16 elems per stage slice -> 128 B rows
#define NST 4
#define A_ST (BM3 * 128)             // 16 KB
#define B_ST (BN3 * 128)             // 32 KB
#define B_OFF (NST * A_ST)           // 64 KB
#define TILE_B (B_OFF + NST * B_ST)  // 192 KB
#define STAGE_TX (A_ST + B_ST)       // 49152
#define KT3 (H / KS3)                // 64
#define SMEM_K3 (TILE_B + 2048)

extern "C" __global__ __launch_bounds__(288, 1)
void k3_gemm_q(const __grid_constant__ CUtensorMap tmA,
               const __grid_constant__ CUtensorMap tmB) {
    extern __shared__ __align__(1024) char smem[];
    const int tid = threadIdx.x, wid = tid >> 5, lane = tid & 31;
    const int bn = blockIdx.x, bm = blockIdx.y;
    const uint32_t dyn = smem_u32(smem);
    const uint32_t bar_full = dyn + TILE_B;
    const uint32_t bar_free = dyn + TILE_B + 32;
    float* qbuf = (float*)(smem + TILE_B + 128);   // 256 floats

    if (tid == 0) {
#pragma unroll
        for (int s = 0; s < NST; s++) {
            mbar_init(bar_full + 8 * s, 1);
            mbar_init(bar_free + 8 * s, 256);
        }
    }
    __syncthreads();

    if (wid == 8) {
        if (elect_one()) {
#pragma unroll
            for (int s = 0; s < NST; s++) {
                mbar_expect_tx(bar_full + 8 * s, STAGE_TX);
                tma2d(dyn + s * A_ST, &tmA, s * KS3, bm * BM3, bar_full + 8 * s);
                tma2d(dyn + B_OFF + s * B_ST, &tmB, s * KS3, bn * BN3, bar_full + 8 * s);
            }
            for (int kt = NST; kt < KT3; kt++) {
                const int s = kt & (NST - 1);
                mbar_wait(bar_free + 8 * s, ((kt - NST) >> 2) & 1);
                mbar_expect_tx(bar_full + 8 * s, STAGE_TX);
                tma2d(dyn + s * A_ST, &tmA, kt * KS3, bm * BM3, bar_full + 8 * s);
                tma2d(dyn + B_OFF + s * B_ST, &tmB, kt * KS3, bn * BN3, bar_full + 8 * s);
            }
        }
    } else {
        const int warpM = wid >> 1, warpN = wid & 1;
        const int a_row = warpM * 32 + (lane & 15);
        const uint32_t a_kb = (lane >> 4) * 16;
        const int b_row = warpN * 128 + (lane & 7) + ((lane >> 4) << 3);
        const uint32_t b_kb = ((lane >> 3) & 1) * 16;

        float acc[2][16][4];
#pragma unroll
        for (int mi = 0; mi < 2; mi++)
#pragma unroll
            for (int ni = 0; ni < 16; ni++)
#pragma unroll
                for (int r = 0; r < 4; r++) acc[mi][ni][r] = 0.f;

        for (int kt = 0; kt < KT3; kt++) {
            const int s = kt & (NST - 1);
            mbar_wait(bar_full + 8 * s, (kt >> 2) & 1);
            const uint32_t abase = dyn + s * A_ST;
            const uint32_t bbase = dyn + B_OFF + s * B_ST;
#pragma unroll
            for (int ks = 0; ks < 4; ks++) {
                uint32_t afr[2][4];
#pragma unroll
                for (int mi = 0; mi < 2; mi++) {
                    uint32_t off = (uint32_t)(a_row + mi * 16) * 128 + ks * 32 + a_kb;
                    ldsm4(afr[mi], abase + swz(off));
                }
                uint32_t bfr[8][4];
#pragma unroll
                for (int nb = 0; nb < 8; nb++) {
                    uint32_t off = (uint32_t)(b_row + nb * 16) * 128 + ks * 32 + b_kb;
                    ldsm4(bfr[nb], bbase + swz(off));
                }
#pragma unroll
                for (int mi = 0; mi < 2; mi++)
#pragma unroll
                    for (int nb = 0; nb < 8; nb++) {
                        mma_bf16(acc[mi][2 * nb],     afr[mi], bfr[nb][0], bfr[nb][1]);
                        mma_bf16(acc[mi][2 * nb + 1], afr[mi], bfr[nb][2], bfr[nb][3]);
                    }
            }
            mbar_arrive(bar_free + 8 * s);
        }

        // square-reduce epilogue (deterministic)
#pragma unroll
        for (int mi = 0; mi < 2; mi++) {
            float p0 = 0.f, p1 = 0.f;
#pragma unroll
            for (int ni = 0; ni < 16; ni++) {
                p0 += acc[mi][ni][0] * acc[mi][ni][0] + acc[mi][ni][1] * acc[mi][ni][1];
                p1 += acc[mi][ni][2] * acc[mi][ni][2] + acc[mi][ni][3] * acc[mi][ni][3];
            }
            p0 += __shfl_xor_sync(0xffffffffu, p0, 1);
            p0 += __shfl_xor_sync(0xffffffffu, p0, 2);
            p1 += __shfl_xor_sync(0xffffffffu, p1, 1);
            p1 += __shfl_xor_sync(0xffffffffu, p1, 2);
            if ((lane & 3) == 0) {
                int row = warpM * 32 + mi * 16 + (lane >> 2);
                qbuf[warpN * 128 + row]     = p0;
                qbuf[warpN * 128 + row + 8] = p1;
            }
        }
    }
    __syncthreads();
    if (tid < 128)
        g_qpart[(size_t)bn * H + bm * BM3 + tid] = qbuf[tid] + qbuf[128 + tid];
}

// ---------------- K4: final reduction ----------------
__global__ __launch_bounds__(128) void k4a(const float* __restrict__ W3) {
    int tid = threadIdx.x;
    int j = blockIdx.x * 128 + tid;
    float q = g_qpart[j] + g_qpart[H + j] + g_qpart[2 * H + j] + g_qpart[3 * H + j];
    float val = W3[j] * g_t[j] * (g_part1[j] - 2.f * g_v0[j] * q);
#pragma unroll
    for (int off = 16; off; off >>= 1) val += __shfl_down_sync(0xffffffffu, val, off);
    __shared__ float red[4];
    if ((tid & 31) == 0) red[tid >> 5] = val;
    __syncthreads();
    if (tid == 0) g_red[blockIdx.x] = red[0] + red[1] + red[2] + red[3];
}
__global__ void k4b(float* __restrict__ out) {
    int lane = threadIdx.x;
    float v = g_red[lane];
#pragma unroll
    for (int off = 16; off; off >>= 1) v += __shfl_down_sync(0xffffffffu, v, off);
    if (lane == 0) out[0] = v;
}

// ---------------- host launch ----------------
typedef CUresult (*EncFnT)(CUtensorMap*, CUtensorMapDataType, cuuint32_t, void*,
                           const cuuint64_t*, const cuuint64_t*, const cuuint32_t*,
                           const cuuint32_t*, CUtensorMapInterleave, CUtensorMapSwizzle,
                           CUtensorMapL2promotion, CUtensorMapFloatOOBfill);

extern "C" void kernel_launch(void* const* d_in, const int* in_sizes, int n_in,
                              void* d_out, int out_size) {
    const float* x  = (const float*)d_in[0];
    const float* W1 = (const float*)d_in[1];
    const float* b1 = (const float*)d_in[2];
    const float* W2 = (const float*)d_in[3];
    const float* b2 = (const float*)d_in[4];
    const float* W3 = (const float*)d_in[5];
    float* out = (float*)d_out;

    EncFnT enc = nullptr;
    cudaDriverEntryPointQueryResult st;
    cudaGetDriverEntryPoint("cuTensorMapEncodeTiled", (void**)&enc, cudaEnableDefault, &st);

    void* w1st_ptr = nullptr;
    void* w2h_ptr  = nullptr;
    cudaGetSymbolAddress(&w1st_ptr, g_W1sT);
    cudaGetSymbolAddress(&w2h_ptr,  g_W2h);

    CUtensorMap tmA{}, tmB{};
    {
        cuuint64_t dims[2] = {(cuuint64_t)H, (cuuint64_t)H};
        cuuint64_t strd[1] = {(cuuint64_t)H * sizeof(__nv_bfloat16)};
        cuuint32_t box[2]  = {KS3, BM3};
        cuuint32_t estr[2] = {1, 1};
        enc(&tmA, CU_TENSOR_MAP_DATA_TYPE_BFLOAT16, 2, w2h_ptr, dims, strd, box, estr,
            CU_TENSOR_MAP_INTERLEAVE_NONE, CU_TENSOR_MAP_SWIZZLE_128B,
            CU_TENSOR_MAP_L2_PROMOTION_L2_128B, CU_TENSOR_MAP_FLOAT_OOB_FILL_NONE);
    }
    {
        cuuint64_t dims[2] = {(cuuint64_t)H, (cuuint64_t)D_IN};
        cuuint64_t strd[1] = {(cuuint64_t)H * sizeof(__nv_bfloat16)};
        cuuint32_t box[2]  = {KS3, BN3};
        cuuint32_t estr[2] = {1, 1};
        enc(&tmB, CU_TENSOR_MAP_DATA_TYPE_BFLOAT16, 2, w1st_ptr, dims, strd, box, estr,
            CU_TENSOR_MAP_INTERLEAVE_NONE, CU_TENSOR_MAP_SWIZZLE_128B,
            CU_TENSOR_MAP_L2_PROMOTION_L2_128B, CU_TENSOR_MAP_FLOAT_OOB_FILL_NONE);
    }

    cudaFuncSetAttribute(k3_gemm_q, cudaFuncAttributeMaxDynamicSharedMemorySize, SMEM_K3);

    k1_layer1<<<H / 8, 256>>>(x, W1, b1);
    k2_layer2<<<H / 8, 256>>>(W2, b2);
    dim3 g3(D_IN / BN3, H / BM3);  // (4, 32)
    k3_gemm_q<<<g3, 288, SMEM_K3>>>(tmA, tmB);
    k4a<<<32, 128>>>(W3);
    k4b<<<1, 32>>>(out);
}

// round 5
// speedup vs baseline: 2.5898x; 1.1069x over previous
#include <cuda_runtime.h>
#include <cuda.h>
#include <cuda_bf16.h>
#include <cstdint>

#define D_IN 1024
#define H    4096

// ---------------- device scratch ----------------
__device__ __align__(1024) __nv_bfloat16 g_W1sT[D_IN * H];  // [i][h] = bf16(s[h]*W1[h][i])
__device__ __align__(1024) __nv_bfloat16 g_W2h[H * H];      // bf16 copy of W2
__device__ __align__(16) float g_u0[H];
__device__ __align__(16) float g_w[H];
__device__ __align__(16) float g_v0[H];
__device__ __align__(16) float g_t[H];
__device__ __align__(16) float g_part1[H];
__device__ __align__(16) float g_qpart[4 * H];
__device__ unsigned int g_ctrA;   // monotonic epoch counters (never reset)
__device__ unsigned int g_ctrB;

// ---------------- PTX helpers ----------------
__device__ __forceinline__ uint32_t smem_u32(const void* p) {
    uint32_t a;
    asm("{ .reg .u64 t; cvta.to.shared.u64 t, %1; cvt.u32.u64 %0, t; }" : "=r"(a) : "l"(p));
    return a;
}
__device__ __forceinline__ uint32_t elect_one() {
    uint32_t p;
    asm volatile("{ .reg .pred P; elect.sync _|P, 0xFFFFFFFF; selp.b32 %0, 1, 0, P; }" : "=r"(p));
    return p;
}
__device__ __forceinline__ void mbar_init(uint32_t mbar, uint32_t cnt) {
    asm volatile("mbarrier.init.shared.b64 [%0], %1;" :: "r"(mbar), "r"(cnt) : "memory");
}
__device__ __forceinline__ void mbar_expect_tx(uint32_t mbar, uint32_t bytes) {
    asm volatile("mbarrier.arrive.expect_tx.shared.b64 _, [%0], %1;" :: "r"(mbar), "r"(bytes) : "memory");
}
__device__ __forceinline__ void mbar_arrive(uint32_t mbar) {
    asm volatile("mbarrier.arrive.shared.b64 _, [%0];" :: "r"(mbar) : "memory");
}
__device__ __forceinline__ void mbar_wait(uint32_t mbar, uint32_t parity) {
    asm volatile(
        "{\n\t.reg .pred P;\n\t"
        "W%=:\n\t"
        "mbarrier.try_wait.parity.acquire.cta.shared::cta.b64 P, [%0], %1, 0x989680;\n\t"
        "@!P bra W%=;\n\t}"
        :: "r"(mbar), "r"(parity) : "memory");
}
__device__ __forceinline__ void tma2d(uint32_t sdst, const void* map, int cx, int cy, uint32_t mbar) {
    asm volatile(
        "cp.async.bulk.tensor.2d.shared::cta.global.tile.mbarrier::complete_tx::bytes "
        "[%0], [%1, {%2, %3}], [%4];"
        :: "r"(sdst), "l"(map), "r"(cx), "r"(cy), "r"(mbar) : "memory");
}
__device__ __forceinline__ void ldsm4(uint32_t* r, uint32_t addr) {
    asm volatile("ldmatrix.sync.aligned.m8n8.x4.shared.b16 {%0,%1,%2,%3}, [%4];"
                 : "=r"(r[0]), "=r"(r[1]), "=r"(r[2]), "=r"(r[3]) : "r"(addr));
}
__device__ __forceinline__ void mma_bf16(float* c, const uint32_t* a, uint32_t b0, uint32_t b1) {
    asm volatile(
        "mma.sync.aligned.m16n8k16.row.col.f32.bf16.bf16.f32 "
        "{%0,%1,%2,%3}, {%4,%5,%6,%7}, {%8,%9}, {%0,%1,%2,%3};"
        : "+f"(c[0]), "+f"(c[1]), "+f"(c[2]), "+f"(c[3])
        : "r"(a[0]), "r"(a[1]), "r"(a[2]), "r"(a[3]), "r"(b0), "r"(b1));
}
__device__ __forceinline__ uint32_t swz(uint32_t off) { return off ^ ((off >> 3) & 0x70); }

// grid-wide sync, monotonic-epoch (no reset needed across graph replays)
__device__ __forceinline__ void gsync(unsigned int* ctr, unsigned int nctas) {
    __syncthreads();
    __threadfence();
    if (threadIdx.x == 0) {
        unsigned int old = atomicAdd(ctr, 1);
        unsigned int target = (old / nctas + 1) * nctas;
        while (*(volatile unsigned int*)ctr < target) {}
    }
    __syncthreads();
    __threadfence();
}

// ================= kernel A: K1 (layer1 + transpose) ; gsync ; K2 (dual GEMV + bf16) =================
#define RS_STRIDE 1033
#define SMEM_KA (32 * RS_STRIDE * 4)   // 132224 B

__global__ __launch_bounds__(512, 1) void kA(const float* __restrict__ x,
                                             const float* __restrict__ W1,
                                             const float* __restrict__ b1,
                                             const float* __restrict__ W2,
                                             const float* __restrict__ b2) {
    extern __shared__ __align__(16) char smem[];
    float* rs = (float*)smem;   // [32][RS_STRIDE]
    const int tid = threadIdx.x, wid = tid >> 5, lane = tid & 31;
    const int c = blockIdx.x;   // 0..127

    // ---- phase 0: rows c*32 .. c*32+31 of layer 1 ----
    const float4* xv = (const float4*)x;
#pragma unroll
    for (int rep = 0; rep < 2; rep++) {
        int hl = wid * 2 + rep;
        int h = c * 32 + hl;
        const float4* row = (const float4*)(W1 + (size_t)h * D_IN);
        float4 buf[8];
        float dot = 0.f, sq = 0.f;
#pragma unroll
        for (int it = 0; it < 8; it++) {
            float4 wv = row[it * 32 + lane];
            float4 xw = xv[it * 32 + lane];
            buf[it] = wv;
            dot += wv.x * xw.x + wv.y * xw.y + wv.z * xw.z + wv.w * xw.w;
            sq  += wv.x * wv.x + wv.y * wv.y + wv.z * wv.z + wv.w * wv.w;
        }
#pragma unroll
        for (int off = 16; off; off >>= 1) {
            dot += __shfl_down_sync(0xffffffffu, dot, off);
            sq  += __shfl_down_sync(0xffffffffu, sq,  off);
        }
        float sv = 0.f;
        if (lane == 0) {
            float a0 = dot + b1[h];
            float u0 = tanhf(a0);
            sv = 1.f - u0 * u0;
            g_u0[h] = u0;
            g_w[h]  = -2.f * u0 * sv * sq;
        }
        sv = __shfl_sync(0xffffffffu, sv, 0);
        float* dst = rs + hl * RS_STRIDE;
#pragma unroll
        for (int it = 0; it < 8; it++) {
            float4 v = buf[it];
            int i = it * 128 + lane * 4;
            dst[i]     = v.x * sv;
            dst[i + 1] = v.y * sv;
            dst[i + 2] = v.z * sv;
            dst[i + 3] = v.w * sv;
        }
    }
    __syncthreads();
    // transpose-write bf16: W1sT[i][c*32 .. +31]
#pragma unroll
    for (int ii = 0; ii < 2; ii++) {
        int i = tid + ii * 512;
        uint32_t pk[16];
#pragma unroll
        for (int r = 0; r < 16; r++) {
            __nv_bfloat162 p = __floats2bfloat162_rn(rs[(2 * r) * RS_STRIDE + i],
                                                     rs[(2 * r + 1) * RS_STRIDE + i]);
            pk[r] = *(uint32_t*)&p;
        }
        uint4* dst = (uint4*)(g_W1sT + (size_t)i * H + c * 32);
        dst[0] = make_uint4(pk[0], pk[1], pk[2], pk[3]);
        dst[1] = make_uint4(pk[4], pk[5], pk[6], pk[7]);
        dst[2] = make_uint4(pk[8], pk[9], pk[10], pk[11]);
        dst[3] = make_uint4(pk[12], pk[13], pk[14], pk[15]);
    }

    gsync(&g_ctrA, 128);   // u0/w must be complete everywhere

    // ---- phase 1: rows c*32 .. +31 of W2: dual GEMV + bf16 copy ----
    const float4* u0v = (const float4*)g_u0;
    const float4* wv4 = (const float4*)g_w;
#pragma unroll
    for (int rep = 0; rep < 2; rep++) {
        int j = c * 32 + wid * 2 + rep;
        const float4* row = (const float4*)(W2 + (size_t)j * H);
        __nv_bfloat16* wout = g_W2h + (size_t)j * H;
        float d1 = 0.f, d2 = 0.f;
#pragma unroll 4
        for (int it = 0; it < 32; it++) {
            float4 a = row[it * 32 + lane];
            float4 u = u0v[it * 32 + lane];
            float4 w = wv4[it * 32 + lane];
            d1 += a.x * u.x + a.y * u.y + a.z * u.z + a.w * u.w;
            d2 += a.x * w.x + a.y * w.y + a.z * w.z + a.w * w.w;
            __nv_bfloat162 q0 = __floats2bfloat162_rn(a.x, a.y);
            __nv_bfloat162 q1 = __floats2bfloat162_rn(a.z, a.w);
            uint2 uo; uo.x = *(uint32_t*)&q0; uo.y = *(uint32_t*)&q1;
            *(uint2*)(wout + it * 128 + lane * 4) = uo;
        }
#pragma unroll
        for (int off = 16; off; off >>= 1) {
            d1 += __shfl_down_sync(0xffffffffu, d1, off);
            d2 += __shfl_down_sync(0xffffffffu, d2, off);
        }
        if (lane == 0) {
            float z0 = d1 + b2[j];
            float v0 = tanhf(z0);
            g_v0[j] = v0;
            g_t[j] = 1.f - v0 * v0;
            g_part1[j] = d2;
        }
    }
}

// ================= kernel B: TMA + mma GEMM + square-reduce + final reduce =================
#define BM3 128
#define BN3 256
#define KS3 64
#define NST 4
#define A_ST (BM3 * 128)                 // 16 KB
#define B_ST (BN3 * 128)                 // 32 KB
#define B_OFF (NST * A_ST)               // 64 KB
#define TILE_B (B_OFF + NST * B_ST)      // 192 KB
#define STAGE_TX (A_ST + B_ST)
#define KT3 (H / KS3)                    // 64
#define SMEM_KB (TILE_B + 1024)

__global__ __launch_bounds__(544, 1) void kB(const __grid_constant__ CUtensorMap tmA,
                                             const __grid_constant__ CUtensorMap tmB,
                                             const float* __restrict__ W3,
                                             float* __restrict__ out) {
    extern __shared__ __align__(1024) char smem[];
    const int tid = threadIdx.x, wid = tid >> 5, lane = tid & 31;
    const int bn = blockIdx.x, bm = blockIdx.y;
    const uint32_t dyn = smem_u32(smem);
    const uint32_t bar_full = dyn + TILE_B;
    const uint32_t bar_free = dyn + TILE_B + 32;

    if (tid == 0) {
#pragma unroll
        for (int s = 0; s < NST; s++) {
            mbar_init(bar_full + 8 * s, 1);
            mbar_init(bar_free + 8 * s, 16);
        }
    }
    __syncthreads();

    float pm[2][2];
    int warpM = 0, warpN = 0;

    if (wid == 16) {
        if (elect_one()) {
#pragma unroll
            for (int s = 0; s < NST; s++) {
                mbar_expect_tx(bar_full + 8 * s, STAGE_TX);
                tma2d(dyn + s * A_ST, &tmA, s * KS3, bm * BM3, bar_full + 8 * s);
                tma2d(dyn + B_OFF + s * B_ST, &tmB, s * KS3, bn * BN3, bar_full + 8 * s);
            }
            for (int kt = NST; kt < KT3; kt++) {
                const int s = kt & (NST - 1);
                mbar_wait(bar_free + 8 * s, ((kt - NST) >> 2) & 1);
                mbar_expect_tx(bar_full + 8 * s, STAGE_TX);
                tma2d(dyn + s * A_ST, &tmA, kt * KS3, bm * BM3, bar_full + 8 * s);
                tma2d(dyn + B_OFF + s * B_ST, &tmB, kt * KS3, bn * BN3, bar_full + 8 * s);
            }
        }
        pm[0][0] = pm[0][1] = pm[1][0] = pm[1][1] = 0.f;
    } else {
        warpM = wid >> 2;            // 0..3, 32 rows
        warpN = wid & 3;             // 0..3, 64 cols
        const int a_row = warpM * 32 + (lane & 15);
        const uint32_t a_kb = (lane >> 4) * 16;
        const int b_row = warpN * 64 + (lane & 7) + ((lane >> 4) << 3);
        const uint32_t b_kb = ((lane >> 3) & 1) * 16;

        float acc[2][8][4];
#pragma unroll
        for (int mi = 0; mi < 2; mi++)
#pragma unroll
            for (int ni = 0; ni < 8; ni++)
#pragma unroll
                for (int r = 0; r < 4; r++) acc[mi][ni][r] = 0.f;

        for (int kt = 0; kt < KT3; kt++) {
            const int s = kt & (NST - 1);
            mbar_wait(bar_full + 8 * s, (kt >> 2) & 1);
            const uint32_t abase = dyn + s * A_ST;
            const uint32_t bbase = dyn + B_OFF + s * B_ST;
#pragma unroll
            for (int ks = 0; ks < 4; ks++) {
                uint32_t afr[2][4];
#pragma unroll
                for (int mi = 0; mi < 2; mi++) {
                    uint32_t off = (uint32_t)(a_row + mi * 16) * 128 + ks * 32 + a_kb;
                    ldsm4(afr[mi], abase + swz(off));
                }
                uint32_t bfr[4][4];
#pragma unroll
                for (int nb = 0; nb < 4; nb++) {
                    uint32_t off = (uint32_t)(b_row + nb * 16) * 128 + ks * 32 + b_kb;
                    ldsm4(bfr[nb], bbase + swz(off));
                }
#pragma unroll
                for (int mi = 0; mi < 2; mi++)
#pragma unroll
                    for (int nb = 0; nb < 4; nb++) {
                        mma_bf16(acc[mi][2 * nb],     afr[mi], bfr[nb][0], bfr[nb][1]);
                        mma_bf16(acc[mi][2 * nb + 1], afr[mi], bfr[nb][2], bfr[nb][3]);
                    }
            }
            if (lane == 0) mbar_arrive(bar_free + 8 * s);
        }
        // per-thread square-reduce into pm
#pragma unroll
        for (int mi = 0; mi < 2; mi++) {
            float p0 = 0.f, p1 = 0.f;
#pragma unroll
            for (int ni = 0; ni < 8; ni++) {
                p0 += acc[mi][ni][0] * acc[mi][ni][0] + acc[mi][ni][1] * acc[mi][ni][1];
                p1 += acc[mi][ni][2] * acc[mi][ni][2] + acc[mi][ni][3] * acc[mi][ni][3];
            }
            p0 += __shfl_xor_sync(0xffffffffu, p0, 1);
            p0 += __shfl_xor_sync(0xffffffffu, p0, 2);
            p1 += __shfl_xor_sync(0xffffffffu, p1, 1);
            p1 += __shfl_xor_sync(0xffffffffu, p1, 2);
            pm[mi][0] = p0;
            pm[mi][1] = p1;
        }
    }
    __syncthreads();   // all smem tile reads done; safe to reuse smem
    float* qbuf = (float*)smem;   // [4][128]
    if (wid < 16 && (lane & 3) == 0) {
#pragma unroll
        for (int mi = 0; mi < 2; mi++) {
            int row = warpM * 32 + mi * 16 + (lane >> 2);
            qbuf[warpN * 128 + row]     = pm[mi][0];
            qbuf[warpN * 128 + row + 8] = pm[mi][1];
        }
    }
    __syncthreads();
    if (tid < 128) {
        float q = qbuf[tid] + qbuf[128 + tid] + qbuf[256 + tid] + qbuf[384 + tid];
        g_qpart[(size_t)bn * H + bm * BM3 + tid] = q;
    }

    // ---- grid arrive; only CTA(0,0) finishes the reduction ----
    const bool is0 = (bn == 0) && (bm == 0);
    __syncthreads();
    __threadfence();
    if (tid == 0) {
        unsigned int old = atomicAdd(&g_ctrB, 1);
        if (is0) {
            unsigned int target = (old / 128 + 1) * 128;
            while (*(volatile unsigned int*)&g_ctrB < target) {}
        }
    }
    if (!is0) return;
    __syncthreads();
    __threadfence();

    float local = 0.f;
    if (tid < 512) {
#pragma unroll
        for (int k = 0; k < 8; k++) {
            int j = tid + k * 512;
            float q = g_qpart[j] + g_qpart[H + j] + g_qpart[2 * H + j] + g_qpart[3 * H + j];
            local += W3[j] * g_t[j] * (g_part1[j] - 2.f * g_v0[j] * q);
        }
    }
#pragma unroll
    for (int off = 16; off; off >>= 1) local += __shfl_down_sync(0xffffffffu, local, off);
    float* red = (float*)smem;
    if (lane == 0) red[wid] = local;
    __syncthreads();
    if (tid == 0) {
        float acc = 0.f;
#pragma unroll
        for (int w = 0; w < 17; w++) acc += red[w];
        out[0] = acc;
    }
}

// ---------------- host launch ----------------
typedef CUresult (*EncFnT)(CUtensorMap*, CUtensorMapDataType, cuuint32_t, void*,
                           const cuuint64_t*, const cuuint64_t*, const cuuint32_t*,
                           const cuuint32_t*, CUtensorMapInterleave, CUtensorMapSwizzle,
                           CUtensorMapL2promotion, CUtensorMapFloatOOBfill);

extern "C" void kernel_launch(void* const* d_in, const int* in_sizes, int n_in,
                              void* d_out, int out_size) {
    const float* x  = (const float*)d_in[0];
    const float* W1 = (const float*)d_in[1];
    const float* b1 = (const float*)d_in[2];
    const float* W2 = (const float*)d_in[3];
    const float* b2 = (const float*)d_in[4];
    const float* W3 = (const float*)d_in[5];
    float* out = (float*)d_out;

    EncFnT enc = nullptr;
    cudaDriverEntryPointQueryResult st;
    cudaGetDriverEntryPoint("cuTensorMapEncodeTiled", (void**)&enc, cudaEnableDefault, &st);

    void* w1st_ptr = nullptr;
    void* w2h_ptr  = nullptr;
    cudaGetSymbolAddress(&w1st_ptr, g_W1sT);
    cudaGetSymbolAddress(&w2h_ptr,  g_W2h);

    CUtensorMap tmA{}, tmB{};
    {
        cuuint64_t dims[2] = {(cuuint64_t)H, (cuuint64_t)H};
        cuuint64_t strd[1] = {(cuuint64_t)H * sizeof(__nv_bfloat16)};
        cuuint32_t box[2]  = {KS3, BM3};
        cuuint32_t estr[2] = {1, 1};
        enc(&tmA, CU_TENSOR_MAP_DATA_TYPE_BFLOAT16, 2, w2h_ptr, dims, strd, box, estr,
            CU_TENSOR_MAP_INTERLEAVE_NONE, CU_TENSOR_MAP_SWIZZLE_128B,
            CU_TENSOR_MAP_L2_PROMOTION_L2_128B, CU_TENSOR_MAP_FLOAT_OOB_FILL_NONE);
    }
    {
        cuuint64_t dims[2] = {(cuuint64_t)H, (cuuint64_t)D_IN};
        cuuint64_t strd[1] = {(cuuint64_t)H * sizeof(__nv_bfloat16)};
        cuuint32_t box[2]  = {KS3, BN3};
        cuuint32_t estr[2] = {1, 1};
        enc(&tmB, CU_TENSOR_MAP_DATA_TYPE_BFLOAT16, 2, w1st_ptr, dims, strd, box, estr,
            CU_TENSOR_MAP_INTERLEAVE_NONE, CU_TENSOR_MAP_SWIZZLE_128B,
            CU_TENSOR_MAP_L2_PROMOTION_L2_128B, CU_TENSOR_MAP_FLOAT_OOB_FILL_NONE);
    }

    cudaFuncSetAttribute(kA, cudaFuncAttributeMaxDynamicSharedMemorySize, SMEM_KA);
    cudaFuncSetAttribute(kB, cudaFuncAttributeMaxDynamicSharedMemorySize, SMEM_KB);

    kA<<<128, 512, SMEM_KA>>>(x, W1, b1, W2, b2);
    dim3 gB(D_IN / BN3, H / BM3);   // (4, 32)
    kB<<<gB, 544, SMEM_KB>>>(tmA, tmB, W3, out);
}